// round 4
// baseline (speedup 1.0000x reference)
#include <cuda_runtime.h>
#include <cuda_bf16.h>
#include <math.h>

// Problem constants
#define BATCH 8
#define SEQ   2048
#define CDIM  1024
#define HDIM  64

// ---------------- scratch (no allocations allowed) ----------------
__device__ float g_q[BATCH * SEQ * HDIM];
__device__ float g_k[BATCH * SEQ * HDIM];
__device__ float g_v[BATCH * SEQ * HDIM];

// ---------------- Kernel 1: QKV projection GEMM ----------------
// C[M=16384, N=64] = X[M, K=1024] * W[K, 64], one of {Wq,Wk,Wv} per blockIdx.z
#define BM 64
#define BN 64
#define BK 16

__global__ void __launch_bounds__(256) qkv_gemm_kernel(
    const float* __restrict__ x,
    const float* __restrict__ Wq,
    const float* __restrict__ Wk,
    const float* __restrict__ Wv)
{
    const float* W = (blockIdx.z == 0) ? Wq : (blockIdx.z == 1) ? Wk : Wv;
    float* out = (blockIdx.z == 0) ? g_q : (blockIdx.z == 1) ? g_k : g_v;

    __shared__ float As[BK][BM + 1];   // As[k][row]
    __shared__ float Bs[BK][BN];       // Bs[k][col]

    const int t  = threadIdx.x;
    const int ty = t >> 4;     // 0..15 -> row group
    const int tx = t & 15;     // 0..15 -> col group
    const int rowBase = blockIdx.x * BM;

    float acc[4][4];
#pragma unroll
    for (int i = 0; i < 4; i++)
#pragma unroll
        for (int j = 0; j < 4; j++) acc[i][j] = 0.0f;

    for (int kBase = 0; kBase < CDIM; kBase += BK) {
        // Load X tile: 64 rows x 16 k  = 256 float4
        {
            int row = t >> 2;          // 0..63
            int k4  = t & 3;           // 0..3
            float4 xv = *reinterpret_cast<const float4*>(
                x + (size_t)(rowBase + row) * CDIM + kBase + k4 * 4);
            As[k4 * 4 + 0][row] = xv.x;
            As[k4 * 4 + 1][row] = xv.y;
            As[k4 * 4 + 2][row] = xv.z;
            As[k4 * 4 + 3][row] = xv.w;
        }
        // Load W tile: 16 k x 64 cols = 256 float4
        {
            int k    = t >> 4;          // 0..15
            int col4 = t & 15;          // 0..15
            float4 wv = *reinterpret_cast<const float4*>(
                W + (size_t)(kBase + k) * HDIM + col4 * 4);
            *reinterpret_cast<float4*>(&Bs[k][col4 * 4]) = wv;
        }
        __syncthreads();

#pragma unroll
        for (int k = 0; k < BK; k++) {
            float a[4], b[4];
#pragma unroll
            for (int i = 0; i < 4; i++) a[i] = As[k][ty * 4 + i];
#pragma unroll
            for (int j = 0; j < 4; j++) b[j] = Bs[k][tx * 4 + j];
#pragma unroll
            for (int i = 0; i < 4; i++)
#pragma unroll
                for (int j = 0; j < 4; j++) acc[i][j] = fmaf(a[i], b[j], acc[i][j]);
        }
        __syncthreads();
    }

#pragma unroll
    for (int i = 0; i < 4; i++) {
        float4 r = make_float4(acc[i][0], acc[i][1], acc[i][2], acc[i][3]);
        *reinterpret_cast<float4*>(
            out + (size_t)(rowBase + ty * 4 + i) * HDIM + tx * 4) = r;
    }
}

// ---------------- Kernel 2: streaming causal attention ----------------
// One block handles a 64-query tile of one batch. Streams 64-key tiles with
// online softmax. O accumulator lives in registers (4x4 microtile/thread).
#define QT 64
#define KT 64

// smem layout (floats), stride 65 to break bank conflicts
#define S_STRIDE 65
#define OFF_Q 0
#define OFF_K (OFF_Q + QT * S_STRIDE)
#define OFF_V (OFF_K + KT * S_STRIDE)
#define OFF_S (OFF_V + KT * S_STRIDE)
#define OFF_M (OFF_S + QT * S_STRIDE)
#define OFF_L (OFF_M + QT)
#define OFF_A (OFF_L + QT)
#define ATTN_SMEM_FLOATS (OFF_A + QT)
#define ATTN_SMEM_BYTES  (ATTN_SMEM_FLOATS * 4)

__global__ void __launch_bounds__(256) attn_kernel(float* __restrict__ out)
{
    extern __shared__ float sm[];
    float* Qs = sm + OFF_Q;
    float* Ks = sm + OFF_K;
    float* Vs = sm + OFF_V;
    float* Ss = sm + OFF_S;
    float* row_m = sm + OFF_M;
    float* row_l = sm + OFF_L;
    float* row_a = sm + OFF_A;

    const int t  = threadIdx.x;
    const int ty = t >> 4;   // 0..15
    const int tx = t & 15;   // 0..15
    const int qt = blockIdx.x;          // 0..31
    const int b  = blockIdx.y;          // 0..7
    const int qBase = qt * QT;
    const float scale = rsqrtf((float)HDIM);

    const float* qg = g_q + (size_t)b * SEQ * HDIM;
    const float* kg = g_k + (size_t)b * SEQ * HDIM;
    const float* vg = g_v + (size_t)b * SEQ * HDIM;

    // Load Q tile: 64 rows x 64 h = 1024 float4, 4 per thread
    {
#pragma unroll
        for (int i = 0; i < 4; i++) {
            int f   = t + i * 256;       // 0..1023
            int row = f >> 4;            // 0..63
            int h4  = f & 15;            // 0..15
            float4 v4 = *reinterpret_cast<const float4*>(
                qg + (size_t)(qBase + row) * HDIM + h4 * 4);
            Qs[row * S_STRIDE + h4 * 4 + 0] = v4.x;
            Qs[row * S_STRIDE + h4 * 4 + 1] = v4.y;
            Qs[row * S_STRIDE + h4 * 4 + 2] = v4.z;
            Qs[row * S_STRIDE + h4 * 4 + 3] = v4.w;
        }
    }
    if (t < QT) {
        row_m[t] = -1e30f;
        row_l[t] = 0.0f;
    }

    float o[4][4];
#pragma unroll
    for (int i = 0; i < 4; i++)
#pragma unroll
        for (int j = 0; j < 4; j++) o[i][j] = 0.0f;

    for (int kt = 0; kt <= qt; kt++) {
        const int kBase = kt * KT;
        __syncthreads();   // protect Ks/Vs/Ss from previous iteration readers

        // Load K and V tiles
#pragma unroll
        for (int i = 0; i < 4; i++) {
            int f   = t + i * 256;
            int row = f >> 4;
            int h4  = f & 15;
            float4 kv4 = *reinterpret_cast<const float4*>(
                kg + (size_t)(kBase + row) * HDIM + h4 * 4);
            Ks[row * S_STRIDE + h4 * 4 + 0] = kv4.x;
            Ks[row * S_STRIDE + h4 * 4 + 1] = kv4.y;
            Ks[row * S_STRIDE + h4 * 4 + 2] = kv4.z;
            Ks[row * S_STRIDE + h4 * 4 + 3] = kv4.w;
            float4 vv4 = *reinterpret_cast<const float4*>(
                vg + (size_t)(kBase + row) * HDIM + h4 * 4);
            Vs[row * S_STRIDE + h4 * 4 + 0] = vv4.x;
            Vs[row * S_STRIDE + h4 * 4 + 1] = vv4.y;
            Vs[row * S_STRIDE + h4 * 4 + 2] = vv4.z;
            Vs[row * S_STRIDE + h4 * 4 + 3] = vv4.w;
        }
        __syncthreads();

        // S = Q K^T * scale  (4x4 microtile per thread)
        float s[4][4];
#pragma unroll
        for (int i = 0; i < 4; i++)
#pragma unroll
            for (int j = 0; j < 4; j++) s[i][j] = 0.0f;

#pragma unroll 8
        for (int h = 0; h < HDIM; h++) {
            float a[4], c[4];
#pragma unroll
            for (int i = 0; i < 4; i++) a[i] = Qs[(ty * 4 + i) * S_STRIDE + h];
#pragma unroll
            for (int j = 0; j < 4; j++) c[j] = Ks[(tx * 4 + j) * S_STRIDE + h];
#pragma unroll
            for (int i = 0; i < 4; i++)
#pragma unroll
                for (int j = 0; j < 4; j++) s[i][j] = fmaf(a[i], c[j], s[i][j]);
        }

        const bool diag = (kt == qt);
#pragma unroll
        for (int i = 0; i < 4; i++) {
            int r = ty * 4 + i;
#pragma unroll
            for (int j = 0; j < 4; j++) {
                int c = tx * 4 + j;
                float v = s[i][j] * scale;
                if (diag && c > r) v = -1e30f;
                Ss[r * S_STRIDE + c] = v;
            }
        }
        __syncthreads();

        // Online softmax: one thread per query row
        if (t < QT) {
            float mo = row_m[t];
            float mn = mo;
            float* srow = Ss + t * S_STRIDE;
#pragma unroll 8
            for (int c = 0; c < KT; c++) mn = fmaxf(mn, srow[c]);
            float alpha = __expf(mo - mn);
            float sum = 0.0f;
#pragma unroll 8
            for (int c = 0; c < KT; c++) {
                float p = __expf(srow[c] - mn);
                srow[c] = p;
                sum += p;
            }
            row_l[t] = row_l[t] * alpha + sum;
            row_m[t] = mn;
            row_a[t] = alpha;
        }
        __syncthreads();

        // O = alpha * O + P V
        float al[4];
#pragma unroll
        for (int i = 0; i < 4; i++) al[i] = row_a[ty * 4 + i];
#pragma unroll
        for (int i = 0; i < 4; i++)
#pragma unroll
            for (int j = 0; j < 4; j++) o[i][j] *= al[i];

#pragma unroll 8
        for (int c = 0; c < KT; c++) {
            float p[4], vv[4];
#pragma unroll
            for (int i = 0; i < 4; i++) p[i] = Ss[(ty * 4 + i) * S_STRIDE + c];
#pragma unroll
            for (int j = 0; j < 4; j++) vv[j] = Vs[c * S_STRIDE + tx * 4 + j];
#pragma unroll
            for (int i = 0; i < 4; i++)
#pragma unroll
                for (int j = 0; j < 4; j++) o[i][j] = fmaf(p[i], vv[j], o[i][j]);
        }
    }
    __syncthreads();

    // Final normalize + store
#pragma unroll
    for (int i = 0; i < 4; i++) {
        int r = ty * 4 + i;
        float inv_l = 1.0f / row_l[r];
        float4 res = make_float4(o[i][0] * inv_l, o[i][1] * inv_l,
                                 o[i][2] * inv_l, o[i][3] * inv_l);
        *reinterpret_cast<float4*>(
            out + ((size_t)b * SEQ + qBase + r) * HDIM + tx * 4) = res;
    }
}

// ---------------- launch ----------------
extern "C" void kernel_launch(void* const* d_in, const int* in_sizes, int n_in,
                              void* d_out, int out_size)
{
    const float* x  = (const float*)d_in[0];
    const float* Wq = (const float*)d_in[1];
    const float* Wk = (const float*)d_in[2];
    const float* Wv = (const float*)d_in[3];
    float* out = (float*)d_out;

    dim3 g1((BATCH * SEQ) / BM, 1, 3);
    qkv_gemm_kernel<<<g1, 256>>>(x, Wq, Wk, Wv);

    cudaFuncSetAttribute(attn_kernel, cudaFuncAttributeMaxDynamicSharedMemorySize,
                         ATTN_SMEM_BYTES);
    dim3 g2(SEQ / QT, BATCH);
    attn_kernel<<<g2, 256, ATTN_SMEM_BYTES>>>(out);
}

// round 6
// speedup vs baseline: 2.5473x; 2.5473x over previous
#include <cuda_runtime.h>
#include <cstdint>
#include <math.h>

#define BATCH 8
#define SEQ   2048
#define CDIM  1024
#define HDIM  64

// ---------------- persistent scratch (q/k/v stored tf32-pre-rounded) ----------------
__device__ float g_q[BATCH * SEQ * HDIM];
__device__ float g_k[BATCH * SEQ * HDIM];
__device__ float g_v[BATCH * SEQ * HDIM];

// ---------------- helpers ----------------
__device__ __forceinline__ uint32_t smem_u32(const void* p) {
    uint32_t a;
    asm("{ .reg .u64 t; cvta.to.shared.u64 t, %1; cvt.u32.u64 %0, t; }" : "=r"(a) : "l"(p));
    return a;
}
__device__ __forceinline__ uint32_t tf32r(float x) {   // round-to-nearest tf32 (bits)
    uint32_t r;
    asm("cvt.rna.tf32.f32 %0, %1;" : "=r"(r) : "f"(x));
    return r;
}
__device__ __forceinline__ void cp16(uint32_t dst, const void* src) {
    asm volatile("cp.async.cg.shared.global [%0], [%1], 16;" :: "r"(dst), "l"(src));
}
#define CP_COMMIT asm volatile("cp.async.commit_group;" ::: "memory")
#define CP_WAIT0  asm volatile("cp.async.wait_group 0;" ::: "memory")
#define CP_WAIT1  asm volatile("cp.async.wait_group 1;" ::: "memory")

// D(16x8,f32) += A(16x8,tf32,row) * B(8x8,tf32,col)
__device__ __forceinline__ void mma8(float* c, const uint32_t* a, uint32_t b0, uint32_t b1) {
    asm volatile(
        "mma.sync.aligned.m16n8k8.row.col.f32.tf32.tf32.f32 "
        "{%0,%1,%2,%3}, {%4,%5,%6,%7}, {%8,%9}, {%0,%1,%2,%3};"
        : "+f"(c[0]), "+f"(c[1]), "+f"(c[2]), "+f"(c[3])
        : "r"(a[0]), "r"(a[1]), "r"(a[2]), "r"(a[3]), "r"(b0), "r"(b1));
}

// ================= Kernel 1: QKV projection =================
// grid (128, 3): blockIdx.x = 128-row M-tile, blockIdx.y = which W.
// SMEM (floats): A0[128*36]@0  A1@4608  B0[32*72]@9216  B1@11520  (55296 B)
#define QKV_SMEM_BYTES 55296

__global__ void __launch_bounds__(256) qkv_mma(
    const float* __restrict__ x,
    const float* __restrict__ Wq,
    const float* __restrict__ Wk,
    const float* __restrict__ Wv)
{
    extern __shared__ float sm[];
    const uint32_t sb = smem_u32(sm);
    const int z = blockIdx.y;
    const float* W   = (z == 0) ? Wq  : (z == 1) ? Wk  : Wv;
    float*       outp = (z == 0) ? g_q : (z == 1) ? g_k : g_v;

    const int t = threadIdx.x, lane = t & 31, warp = t >> 5;
    const int g = lane >> 2, t4 = lane & 3;
    const int wm = warp >> 1, wn = warp & 1;          // 4 M-groups x 2 N-groups
    const int rowBase = blockIdx.x * 128;

    float acc[2][4][4];
#pragma unroll
    for (int a = 0; a < 2; a++)
#pragma unroll
        for (int b = 0; b < 4; b++)
#pragma unroll
            for (int c = 0; c < 4; c++) acc[a][b][c] = 0.0f;

    auto issue = [&](int c, int st) {
        uint32_t ab = sb + (uint32_t)st * 4608u * 4u;
#pragma unroll
        for (int i = 0; i < 4; i++) {                  // A chunk: 128x32 = 1024 float4
            int idx = t + i * 256;
            int r = idx >> 3, j = idx & 7;
            cp16(ab + (uint32_t)(r * 36 + j * 4) * 4u,
                 x + (size_t)(rowBase + r) * CDIM + c * 32 + j * 4);
        }
        uint32_t bb = sb + (9216u + (uint32_t)st * 2304u) * 4u;
#pragma unroll
        for (int i = 0; i < 2; i++) {                  // B chunk: 32x64 = 512 float4
            int idx = t + i * 256;
            int k = idx >> 4, j = idx & 15;
            cp16(bb + (uint32_t)(k * 72 + j * 4) * 4u,
                 W + (size_t)(c * 32 + k) * HDIM + j * 4);
        }
    };

    issue(0, 0); CP_COMMIT;

    for (int c = 0; c < 32; c++) {
        const int st = c & 1;
        if (c < 31) { issue(c + 1, st ^ 1); CP_COMMIT; CP_WAIT1; }
        else        { CP_WAIT0; }
        __syncthreads();

        const float* As = sm + st * 4608;
        const float* Bs = sm + 9216 + st * 2304;

#pragma unroll
        for (int kk = 0; kk < 4; kk++) {
            const int k0 = kk * 8;
            uint32_t af[2][4];
#pragma unroll
            for (int mt = 0; mt < 2; mt++) {
                int r = wm * 32 + mt * 16;
                af[mt][0] = tf32r(As[(r + g)     * 36 + k0 + t4]);
                af[mt][1] = tf32r(As[(r + g + 8) * 36 + k0 + t4]);
                af[mt][2] = tf32r(As[(r + g)     * 36 + k0 + t4 + 4]);
                af[mt][3] = tf32r(As[(r + g + 8) * 36 + k0 + t4 + 4]);
            }
#pragma unroll
            for (int nt = 0; nt < 4; nt++) {
                int n = wn * 32 + nt * 8 + g;
                uint32_t b0 = tf32r(Bs[(k0 + t4)     * 72 + n]);
                uint32_t b1 = tf32r(Bs[(k0 + t4 + 4) * 72 + n]);
                mma8(acc[0][nt], af[0], b0, b1);
                mma8(acc[1][nt], af[1], b0, b1);
            }
        }
        __syncthreads();
    }

    // epilogue: round to tf32 (attention consumes tf32 directly) and store
#pragma unroll
    for (int mt = 0; mt < 2; mt++) {
        int r0 = rowBase + wm * 32 + mt * 16 + g;
#pragma unroll
        for (int nt = 0; nt < 4; nt++) {
            int cc = wn * 32 + nt * 8 + 2 * t4;
            float2 v0 = { __uint_as_float(tf32r(acc[mt][nt][0])),
                          __uint_as_float(tf32r(acc[mt][nt][1])) };
            *reinterpret_cast<float2*>(outp + (size_t)r0 * HDIM + cc) = v0;
            float2 v1 = { __uint_as_float(tf32r(acc[mt][nt][2])),
                          __uint_as_float(tf32r(acc[mt][nt][3])) };
            *reinterpret_cast<float2*>(outp + (size_t)(r0 + 8) * HDIM + cc) = v1;
        }
    }
}

// ================= Kernel 2: causal attention =================
// grid (16, 8): 128-query tile per CTA, 8 warps x 16 rows.
// SMEM (floats): K0[128*68]@0  K1@8704  V0[128*72]@17408  V1@26624  P[128*132]@35840
// total 52736 floats = 210944 B. Q staged in the P region before the loop.
#define ATTN_SMEM_BYTES 210944

__global__ void __launch_bounds__(256) attn_mma(float* __restrict__ outp)
{
    extern __shared__ float sm[];
    const uint32_t sb = smem_u32(sm);
    const int t = threadIdx.x, lane = t & 31, warp = t >> 5;
    const int g = lane >> 2, t4 = lane & 3;
    const int qt = blockIdx.x, b = blockIdx.y;
    const int qBase = qt * 128;

    float* Ps = sm + 35840;                 // stride 132

    // ---- stage Q (already tf32-rounded) and build register fragments ----
    const float* qg = g_q + ((size_t)b * SEQ + qBase) * HDIM;
#pragma unroll
    for (int i = 0; i < 8; i++) {
        int idx = t + i * 256;
        int r = idx >> 4, j = idx & 15;
        *reinterpret_cast<float4*>(Ps + r * 68 + j * 4) =
            *reinterpret_cast<const float4*>(qg + (size_t)r * HDIM + j * 4);
    }
    __syncthreads();

    uint32_t qf[8][4];
    {
        int r0 = warp * 16;
#pragma unroll
        for (int kk = 0; kk < 8; kk++) {
            qf[kk][0] = __float_as_uint(Ps[(r0 + g)     * 68 + kk * 8 + t4]);
            qf[kk][1] = __float_as_uint(Ps[(r0 + g + 8) * 68 + kk * 8 + t4]);
            qf[kk][2] = __float_as_uint(Ps[(r0 + g)     * 68 + kk * 8 + t4 + 4]);
            qf[kk][3] = __float_as_uint(Ps[(r0 + g + 8) * 68 + kk * 8 + t4 + 4]);
        }
    }
    __syncthreads();   // Q staging reads done before P writes alias the region

    float oacc[8][4];
#pragma unroll
    for (int a = 0; a < 8; a++)
#pragma unroll
        for (int c = 0; c < 4; c++) oacc[a][c] = 0.0f;
    float rs0 = 0.0f, rs1 = 0.0f;

    const float* kg = g_k + (size_t)b * SEQ * HDIM;
    const float* vg = g_v + (size_t)b * SEQ * HDIM;

    auto issue = [&](int kt, int st) {
        uint32_t kb = sb + (uint32_t)st * 8704u * 4u;
        uint32_t vb = sb + (17408u + (uint32_t)st * 9216u) * 4u;
#pragma unroll
        for (int i = 0; i < 8; i++) {
            int idx = t + i * 256;
            int r = idx >> 4, j = idx & 15;
            cp16(kb + (uint32_t)(r * 68 + j * 4) * 4u,
                 kg + (size_t)(kt * 128 + r) * HDIM + j * 4);
            cp16(vb + (uint32_t)(r * 72 + j * 4) * 4u,
                 vg + (size_t)(kt * 128 + r) * HDIM + j * 4);
        }
    };

    issue(0, 0); CP_COMMIT;

    for (int kt = 0; kt <= qt; kt++) {
        const int st = kt & 1;
        if (kt < qt) { issue(kt + 1, st ^ 1); CP_COMMIT; CP_WAIT1; }
        else         { CP_WAIT0; }
        __syncthreads();

        const float* Kst = sm + st * 8704;          // stride 68
        const float* Vst = sm + 17408 + st * 9216;  // stride 72

        // ---- S = Q @ K^T ----
        float sacc[16][4];
#pragma unroll
        for (int a = 0; a < 16; a++)
#pragma unroll
            for (int c = 0; c < 4; c++) sacc[a][c] = 0.0f;

#pragma unroll
        for (int nt = 0; nt < 16; nt++) {
#pragma unroll
            for (int kk = 0; kk < 8; kk++) {
                uint32_t b0 = __float_as_uint(Kst[(nt * 8 + g) * 68 + kk * 8 + t4]);
                uint32_t b1 = __float_as_uint(Kst[(nt * 8 + g) * 68 + kk * 8 + t4 + 4]);
                mma8(sacc[nt], qf[kk], b0, b1);
            }
        }

        // ---- mask + exp + row-sum + store P (warp-private rows) ----
        const bool dtile = (kt == qt);
        const int r0l = warp * 16 + g;
#pragma unroll
        for (int nt = 0; nt < 16; nt++) {
            int c0 = nt * 8 + 2 * t4;
            float p00 = __expf(sacc[nt][0] * 0.125f);
            float p01 = __expf(sacc[nt][1] * 0.125f);
            float p10 = __expf(sacc[nt][2] * 0.125f);
            float p11 = __expf(sacc[nt][3] * 0.125f);
            if (dtile) {
                if (c0     > r0l)     p00 = 0.0f;
                if (c0 + 1 > r0l)     p01 = 0.0f;
                if (c0     > r0l + 8) p10 = 0.0f;
                if (c0 + 1 > r0l + 8) p11 = 0.0f;
            }
            rs0 += p00 + p01;
            rs1 += p10 + p11;
            float2 w0 = { __uint_as_float(tf32r(p00)), __uint_as_float(tf32r(p01)) };
            *reinterpret_cast<float2*>(Ps + r0l * 132 + c0) = w0;
            float2 w1 = { __uint_as_float(tf32r(p10)), __uint_as_float(tf32r(p11)) };
            *reinterpret_cast<float2*>(Ps + (r0l + 8) * 132 + c0) = w1;
        }
        __syncwarp();   // cross-lane P visibility within the warp

        // ---- O += P @ V ----
#pragma unroll
        for (int kk = 0; kk < 16; kk++) {
            uint32_t af[4];
            af[0] = __float_as_uint(Ps[(warp * 16 + g)     * 132 + kk * 8 + t4]);
            af[1] = __float_as_uint(Ps[(warp * 16 + g + 8) * 132 + kk * 8 + t4]);
            af[2] = __float_as_uint(Ps[(warp * 16 + g)     * 132 + kk * 8 + t4 + 4]);
            af[3] = __float_as_uint(Ps[(warp * 16 + g + 8) * 132 + kk * 8 + t4 + 4]);
#pragma unroll
            for (int nt = 0; nt < 8; nt++) {
                uint32_t b0 = __float_as_uint(Vst[(kk * 8 + t4)     * 72 + nt * 8 + g]);
                uint32_t b1 = __float_as_uint(Vst[(kk * 8 + t4 + 4) * 72 + nt * 8 + g]);
                mma8(oacc[nt], af, b0, b1);
            }
        }
        __syncthreads();   // all warps done with this K/V stage
    }

    // ---- normalize + store ----
    rs0 += __shfl_xor_sync(0xffffffffu, rs0, 1);
    rs0 += __shfl_xor_sync(0xffffffffu, rs0, 2);
    rs1 += __shfl_xor_sync(0xffffffffu, rs1, 1);
    rs1 += __shfl_xor_sync(0xffffffffu, rs1, 2);
    const float inv0 = 1.0f / rs0;
    const float inv1 = 1.0f / rs1;

    float* og = outp + ((size_t)b * SEQ + qBase) * HDIM;
    const int r0 = warp * 16 + g;
#pragma unroll
    for (int nt = 0; nt < 8; nt++) {
        int cc = nt * 8 + 2 * t4;
        float2 v0 = { oacc[nt][0] * inv0, oacc[nt][1] * inv0 };
        *reinterpret_cast<float2*>(og + (size_t)r0 * HDIM + cc) = v0;
        float2 v1 = { oacc[nt][2] * inv1, oacc[nt][3] * inv1 };
        *reinterpret_cast<float2*>(og + (size_t)(r0 + 8) * HDIM + cc) = v1;
    }
}

// ---------------- launch ----------------
extern "C" void kernel_launch(void* const* d_in, const int* in_sizes, int n_in,
                              void* d_out, int out_size)
{
    const float* x  = (const float*)d_in[0];
    const float* Wq = (const float*)d_in[1];
    const float* Wk = (const float*)d_in[2];
    const float* Wv = (const float*)d_in[3];
    float* out = (float*)d_out;

    cudaFuncSetAttribute(qkv_mma, cudaFuncAttributeMaxDynamicSharedMemorySize,
                         QKV_SMEM_BYTES);
    qkv_mma<<<dim3((BATCH * SEQ) / 128, 3), 256, QKV_SMEM_BYTES>>>(x, Wq, Wk, Wv);

    cudaFuncSetAttribute(attn_mma, cudaFuncAttributeMaxDynamicSharedMemorySize,
                         ATTN_SMEM_BYTES);
    attn_mma<<<dim3(SEQ / 128, BATCH), 256, ATTN_SMEM_BYTES>>>(out);
}

// round 7
// speedup vs baseline: 4.4703x; 1.7549x over previous
#include <cuda_runtime.h>
#include <cstdint>
#include <math.h>

#define BATCH 8
#define SEQ   2048
#define CDIM  1024
#define HDIM  64

// ---------------- persistent scratch ----------------
__device__ float g_wt[3 * HDIM * CDIM];            // [3*64][1024] W^T, tf32-rounded
__device__ float g_q[BATCH * SEQ * HDIM];          // tf32-rounded
__device__ float g_k[BATCH * SEQ * HDIM];
__device__ float g_v[BATCH * SEQ * HDIM];
__device__ float g_partO[3][BATCH * SEQ * HDIM];   // split partial O
__device__ float g_partL[3][BATCH * SEQ];          // split partial row-sums

// ---------------- helpers ----------------
__device__ __forceinline__ uint32_t smem_u32(const void* p) {
    uint32_t a;
    asm("{ .reg .u64 t; cvta.to.shared.u64 t, %1; cvt.u32.u64 %0, t; }" : "=r"(a) : "l"(p));
    return a;
}
__device__ __forceinline__ uint32_t tf32r(float x) {
    uint32_t r;
    asm("cvt.rna.tf32.f32 %0, %1;" : "=r"(r) : "f"(x));
    return r;
}
__device__ __forceinline__ void cp16(uint32_t dst, const void* src) {
    asm volatile("cp.async.cg.shared.global [%0], [%1], 16;" :: "r"(dst), "l"(src));
}
#define CP_COMMIT asm volatile("cp.async.commit_group;" ::: "memory")
#define CP_WAIT0  asm volatile("cp.async.wait_group 0;" ::: "memory")
#define CP_WAIT1  asm volatile("cp.async.wait_group 1;" ::: "memory")

__device__ __forceinline__ void mma8(float* c, const uint32_t* a, uint32_t b0, uint32_t b1) {
    asm volatile(
        "mma.sync.aligned.m16n8k8.row.col.f32.tf32.tf32.f32 "
        "{%0,%1,%2,%3}, {%4,%5,%6,%7}, {%8,%9}, {%0,%1,%2,%3};"
        : "+f"(c[0]), "+f"(c[1]), "+f"(c[2]), "+f"(c[3])
        : "r"(a[0]), "r"(a[1]), "r"(a[2]), "r"(a[3]), "r"(b0), "r"(b1));
}

// ================= Kernel 0: W transpose + tf32 round =================
__global__ void wt_kernel(const float* __restrict__ Wq,
                          const float* __restrict__ Wk,
                          const float* __restrict__ Wv)
{
    const float* W = (blockIdx.z == 0) ? Wq : (blockIdx.z == 1) ? Wk : Wv;
    __shared__ float tile[32][33];
    int c0 = blockIdx.x * 32, h0 = blockIdx.y * 32;
    tile[threadIdx.y][threadIdx.x] = W[(size_t)(c0 + threadIdx.y) * HDIM + h0 + threadIdx.x];
    __syncthreads();
    g_wt[(size_t)blockIdx.z * HDIM * CDIM + (size_t)(h0 + threadIdx.y) * CDIM + c0 + threadIdx.x] =
        __uint_as_float(tf32r(tile[threadIdx.x][threadIdx.y]));
}

// ================= Kernel 1: fused QKV projection =================
// grid 256: 64-row M-tile per CTA. B tile = 192 rows (Wq|Wk|Wv, n-major) x 32 k.
// SMEM floats: A0[64*36]@0  A1@2304  B0[192*36]@4608  B1@11520  -> 73728 B
#define QKV_SMEM_BYTES 73728

__global__ void __launch_bounds__(256) qkv_mma(const float* __restrict__ x)
{
    extern __shared__ float sm[];
    const uint32_t sb = smem_u32(sm);
    const int t = threadIdx.x, lane = t & 31, warp = t >> 5;
    const int g = lane >> 2, t4 = lane & 3;
    const int wm = warp >> 2, wn = warp & 3;          // 2 M-groups x 4 N-groups
    const int Mbase = blockIdx.x * 64;

    float acc[2][6][4];
#pragma unroll
    for (int a = 0; a < 2; a++)
#pragma unroll
        for (int b = 0; b < 6; b++)
#pragma unroll
            for (int c = 0; c < 4; c++) acc[a][b][c] = 0.0f;

    auto issue = [&](int c, int st) {
        uint32_t ab = sb + (uint32_t)st * 2304u * 4u;
#pragma unroll
        for (int i = 0; i < 2; i++) {                  // A: 64x32 = 512 float4
            int idx = t + i * 256;
            int r = idx >> 3, j = idx & 7;
            cp16(ab + (uint32_t)(r * 36 + j * 4) * 4u,
                 x + (size_t)(Mbase + r) * CDIM + c * 32 + j * 4);
        }
        uint32_t bb = sb + (4608u + (uint32_t)st * 6912u) * 4u;
#pragma unroll
        for (int i = 0; i < 6; i++) {                  // B: 192x32 = 1536 float4
            int idx = t + i * 256;
            int n = idx >> 3, j = idx & 7;
            cp16(bb + (uint32_t)(n * 36 + j * 4) * 4u,
                 g_wt + (size_t)n * CDIM + c * 32 + j * 4);
        }
    };

    issue(0, 0); CP_COMMIT;

    for (int c = 0; c < 32; c++) {
        const int st = c & 1;
        if (c < 31) { issue(c + 1, st ^ 1); CP_COMMIT; CP_WAIT1; }
        else        { CP_WAIT0; }
        __syncthreads();

        const float* As = sm + st * 2304;
        const float* Bs = sm + 4608 + st * 6912;

#pragma unroll
        for (int kk = 0; kk < 4; kk++) {
            const int k0 = kk * 8;
            uint32_t af[2][4];
#pragma unroll
            for (int mt = 0; mt < 2; mt++) {
                int r = wm * 32 + mt * 16;
                af[mt][0] = tf32r(As[(r + g)     * 36 + k0 + t4]);
                af[mt][1] = tf32r(As[(r + g + 8) * 36 + k0 + t4]);
                af[mt][2] = tf32r(As[(r + g)     * 36 + k0 + t4 + 4]);
                af[mt][3] = tf32r(As[(r + g + 8) * 36 + k0 + t4 + 4]);
            }
#pragma unroll
            for (int nt = 0; nt < 6; nt++) {
                int n = wn * 48 + nt * 8 + g;          // n-major B: conflict-free
                uint32_t b0 = __float_as_uint(Bs[n * 36 + k0 + t4]);
                uint32_t b1 = __float_as_uint(Bs[n * 36 + k0 + t4 + 4]);
                mma8(acc[0][nt], af[0], b0, b1);
                mma8(acc[1][nt], af[1], b0, b1);
            }
        }
        __syncthreads();
    }

    // epilogue: route each 8-col tile to q/k/v, round to tf32
#pragma unroll
    for (int mt = 0; mt < 2; mt++) {
        int r0 = Mbase + wm * 32 + mt * 16 + g;
#pragma unroll
        for (int nt = 0; nt < 6; nt++) {
            int ncol = wn * 48 + nt * 8 + 2 * t4;
            int w = ncol >> 6, cc = ncol & 63;
            float* outp = (w == 0) ? g_q : (w == 1) ? g_k : g_v;
            float2 v0 = { __uint_as_float(tf32r(acc[mt][nt][0])),
                          __uint_as_float(tf32r(acc[mt][nt][1])) };
            *reinterpret_cast<float2*>(outp + (size_t)r0 * HDIM + cc) = v0;
            float2 v1 = { __uint_as_float(tf32r(acc[mt][nt][2])),
                          __uint_as_float(tf32r(acc[mt][nt][3])) };
            *reinterpret_cast<float2*>(outp + (size_t)(r0 + 8) * HDIM + cc) = v1;
        }
    }
}

// ================= Kernel 2: split-K causal attention =================
// 240 CTAs: (b, qt, split). nsplit(qt) = ceil((qt+1)/6) -> max 6 key-tile iters.
// SMEM floats: K[128*68]@0  V[128*72]@8704  P/Q[128*68]@17920  -> 106496 B
#define ATTN_SMEM_BYTES 106496

__global__ void __launch_bounds__(256, 2) attn_split()
{
    extern __shared__ float sm[];
    const uint32_t sb = smem_u32(sm);
    const int t = threadIdx.x, lane = t & 31, warp = t >> 5;
    const int g = lane >> 2, t4 = lane & 3;

    const int bid = blockIdx.x;
    const int b = bid / 30, r = bid % 30;
    int qt, s;
    if (r < 6)        { qt = r;                s = 0; }
    else if (r < 18)  { qt = 6 + (r - 6) / 2;  s = (r - 6) % 2; }
    else              { qt = 12 + (r - 18) / 3; s = (r - 18) % 3; }
    const int len = qt + 1, ns = (qt + 6) / 6;
    const int k0t = s * len / ns, k1t = (s + 1) * len / ns;
    const int qBase = qt * 128;

    float* Ks = sm;                  // stride 68
    float* Vs = sm + 8704;           // stride 72
    float* Ps = sm + 17920;          // stride 68 (also Q staging)

    const float* kg = g_k + (size_t)b * SEQ * HDIM;
    const float* vg = g_v + (size_t)b * SEQ * HDIM;

    auto issueKV = [&](int kt) {
#pragma unroll
        for (int i = 0; i < 8; i++) {
            int idx = t + i * 256;
            int rr = idx >> 4, j = idx & 15;
            cp16(sb + (uint32_t)(rr * 68 + j * 4) * 4u,
                 kg + (size_t)(kt * 128 + rr) * HDIM + j * 4);
            cp16(sb + (uint32_t)(8704 + rr * 72 + j * 4) * 4u,
                 vg + (size_t)(kt * 128 + rr) * HDIM + j * 4);
        }
    };

    issueKV(k0t); CP_COMMIT;

    // stage Q, build register fragments
    const float* qg = g_q + ((size_t)b * SEQ + qBase) * HDIM;
#pragma unroll
    for (int i = 0; i < 8; i++) {
        int idx = t + i * 256;
        int rr = idx >> 4, j = idx & 15;
        *reinterpret_cast<float4*>(Ps + rr * 68 + j * 4) =
            *reinterpret_cast<const float4*>(qg + (size_t)rr * HDIM + j * 4);
    }
    __syncthreads();
    uint32_t qf[8][4];
    {
        int r0 = warp * 16;
#pragma unroll
        for (int kk = 0; kk < 8; kk++) {
            qf[kk][0] = __float_as_uint(Ps[(r0 + g)     * 68 + kk * 8 + t4]);
            qf[kk][1] = __float_as_uint(Ps[(r0 + g + 8) * 68 + kk * 8 + t4]);
            qf[kk][2] = __float_as_uint(Ps[(r0 + g)     * 68 + kk * 8 + t4 + 4]);
            qf[kk][3] = __float_as_uint(Ps[(r0 + g + 8) * 68 + kk * 8 + t4 + 4]);
        }
    }
    __syncthreads();

    float oacc[8][4];
#pragma unroll
    for (int a = 0; a < 8; a++)
#pragma unroll
        for (int c = 0; c < 4; c++) oacc[a][c] = 0.0f;
    float rs0 = 0.0f, rs1 = 0.0f;
    const int r0l = warp * 16 + g;

    for (int kt = k0t; kt < k1t; kt++) {
        CP_WAIT0;
        __syncthreads();
        const bool dtile = (kt == qt);

#pragma unroll
        for (int h = 0; h < 2; h++) {
            // ---- S half: 128q x 64keys ----
            float sacc[8][4];
#pragma unroll
            for (int a = 0; a < 8; a++)
#pragma unroll
                for (int c = 0; c < 4; c++) sacc[a][c] = 0.0f;
#pragma unroll
            for (int nt = 0; nt < 8; nt++) {
                const int krow = h * 64 + nt * 8 + g;
#pragma unroll
                for (int kk = 0; kk < 8; kk++) {
                    uint32_t b0 = __float_as_uint(Ks[krow * 68 + kk * 8 + t4]);
                    uint32_t b1 = __float_as_uint(Ks[krow * 68 + kk * 8 + t4 + 4]);
                    mma8(sacc[nt], qf[kk], b0, b1);
                }
            }
            // ---- exp + mask + row-sum + store P half ----
#pragma unroll
            for (int nt = 0; nt < 8; nt++) {
                int c0 = h * 64 + nt * 8 + 2 * t4;         // col within 128-key tile
                float p00 = __expf(sacc[nt][0] * 0.125f);
                float p01 = __expf(sacc[nt][1] * 0.125f);
                float p10 = __expf(sacc[nt][2] * 0.125f);
                float p11 = __expf(sacc[nt][3] * 0.125f);
                if (dtile) {
                    if (c0     > r0l)     p00 = 0.0f;
                    if (c0 + 1 > r0l)     p01 = 0.0f;
                    if (c0     > r0l + 8) p10 = 0.0f;
                    if (c0 + 1 > r0l + 8) p11 = 0.0f;
                }
                rs0 += p00 + p01;
                rs1 += p10 + p11;
                int pc = nt * 8 + 2 * t4;                  // col within P half-buffer
                float2 w0 = { __uint_as_float(tf32r(p00)), __uint_as_float(tf32r(p01)) };
                *reinterpret_cast<float2*>(Ps + r0l * 68 + pc) = w0;
                float2 w1 = { __uint_as_float(tf32r(p10)), __uint_as_float(tf32r(p11)) };
                *reinterpret_cast<float2*>(Ps + (r0l + 8) * 68 + pc) = w1;
            }
            __syncwarp();
            // ---- O += P_half @ V[half] ----
#pragma unroll
            for (int kk = 0; kk < 8; kk++) {
                uint32_t af[4];
                af[0] = __float_as_uint(Ps[(warp * 16 + g)     * 68 + kk * 8 + t4]);
                af[1] = __float_as_uint(Ps[(warp * 16 + g + 8) * 68 + kk * 8 + t4]);
                af[2] = __float_as_uint(Ps[(warp * 16 + g)     * 68 + kk * 8 + t4 + 4]);
                af[3] = __float_as_uint(Ps[(warp * 16 + g + 8) * 68 + kk * 8 + t4 + 4]);
                const int vrow = h * 64 + kk * 8 + t4;
#pragma unroll
                for (int nt = 0; nt < 8; nt++) {
                    uint32_t b0 = __float_as_uint(Vs[vrow       * 72 + nt * 8 + g]);
                    uint32_t b1 = __float_as_uint(Vs[(vrow + 4) * 72 + nt * 8 + g]);
                    mma8(oacc[nt], af, b0, b1);
                }
            }
            __syncwarp();
        }
        __syncthreads();                    // K/V reads done before refill
        if (kt + 1 < k1t) { issueKV(kt + 1); CP_COMMIT; }
    }

    // ---- partial epilogue ----
    rs0 += __shfl_xor_sync(0xffffffffu, rs0, 1);
    rs0 += __shfl_xor_sync(0xffffffffu, rs0, 2);
    rs1 += __shfl_xor_sync(0xffffffffu, rs1, 1);
    rs1 += __shfl_xor_sync(0xffffffffu, rs1, 2);

    float* po = g_partO[s] + ((size_t)b * SEQ + qBase + r0l) * HDIM;
#pragma unroll
    for (int nt = 0; nt < 8; nt++) {
        int cc = nt * 8 + 2 * t4;
        float2 v0 = { oacc[nt][0], oacc[nt][1] };
        *reinterpret_cast<float2*>(po + cc) = v0;
        float2 v1 = { oacc[nt][2], oacc[nt][3] };
        *reinterpret_cast<float2*>(po + (size_t)8 * HDIM + cc) = v1;
    }
    if (t4 == 0) {
        g_partL[s][(size_t)b * SEQ + qBase + r0l]     = rs0;
        g_partL[s][(size_t)b * SEQ + qBase + r0l + 8] = rs1;
    }
}

// ================= Kernel 3: combine splits + normalize =================
__global__ void __launch_bounds__(256) combine_kernel(float* __restrict__ out)
{
    int gid = blockIdx.x * 256 + threadIdx.x;       // one float4 per thread
    int row = gid >> 4;
    int qt = (row & (SEQ - 1)) >> 7;
    int ns = (qt + 6) / 6;

    float4 o = reinterpret_cast<const float4*>(g_partO[0])[gid];
    float  l = g_partL[0][row];
    if (ns > 1) {
        float4 o1 = reinterpret_cast<const float4*>(g_partO[1])[gid];
        o.x += o1.x; o.y += o1.y; o.z += o1.z; o.w += o1.w;
        l += g_partL[1][row];
    }
    if (ns > 2) {
        float4 o2 = reinterpret_cast<const float4*>(g_partO[2])[gid];
        o.x += o2.x; o.y += o2.y; o.z += o2.z; o.w += o2.w;
        l += g_partL[2][row];
    }
    float inv = 1.0f / l;
    o.x *= inv; o.y *= inv; o.z *= inv; o.w *= inv;
    reinterpret_cast<float4*>(out)[gid] = o;
}

// ---------------- launch ----------------
extern "C" void kernel_launch(void* const* d_in, const int* in_sizes, int n_in,
                              void* d_out, int out_size)
{
    const float* x  = (const float*)d_in[0];
    const float* Wq = (const float*)d_in[1];
    const float* Wk = (const float*)d_in[2];
    const float* Wv = (const float*)d_in[3];
    float* out = (float*)d_out;

    wt_kernel<<<dim3(CDIM / 32, HDIM / 32, 3), dim3(32, 32)>>>(Wq, Wk, Wv);

    cudaFuncSetAttribute(qkv_mma, cudaFuncAttributeMaxDynamicSharedMemorySize,
                         QKV_SMEM_BYTES);
    qkv_mma<<<(BATCH * SEQ) / 64, 256, QKV_SMEM_BYTES>>>(x);

    cudaFuncSetAttribute(attn_split, cudaFuncAttributeMaxDynamicSharedMemorySize,
                         ATTN_SMEM_BYTES);
    attn_split<<<240, 256, ATTN_SMEM_BYTES>>>();

    combine_kernel<<<(BATCH * SEQ * HDIM / 4) / 256, 256>>>(out);
}